// round 8
// baseline (speedup 1.0000x reference)
#include <cuda_runtime.h>
#include <cuda_fp16.h>

#define NP 110000
#define NT 20000
#define NG 10000
#define NTOT (NP + NT + NG)   // 140000
#define EE 500000
#define DD 64

#define SCAN_BLK ((NTOT + 1023) / 1024)   // 137

// ---- scratch (static device memory; no allocations allowed) ----
__device__ int   g_deg[NTOT];
__device__ int   g_off[NTOT];
__device__ int   g_cur[NTOT];
__device__ int   g_total;
__device__ int   g_adj[3 * EE];
__device__ float g_dinv[NTOT];
__device__ __align__(16) __half g_embs[(size_t)NTOT * DD];  // emb * dinv (fp16)
__device__ __align__(16) __half g_x1h[(size_t)NTOT * DD];   // x1 (true)
__device__ __align__(16) __half g_x1s[(size_t)NTOT * DD];   // x1 * dinv
__device__ __align__(16) __half g_x2h[(size_t)NTOT * DD];   // final table p

// ---------------------------------------------------------------
__global__ void degree_kernel(const int* __restrict__ up,
                              const int* __restrict__ ut,
                              const int* __restrict__ ug) {
    const int Q = EE / 4;
    int i = blockIdx.x * blockDim.x + threadIdx.x;
    if (i < Q) {
        int4 d = reinterpret_cast<const int4*>(up + EE)[i];
        atomicAdd(&g_deg[d.x], 1); atomicAdd(&g_deg[d.y], 1);
        atomicAdd(&g_deg[d.z], 1); atomicAdd(&g_deg[d.w], 1);
    } else if (i < 2 * Q) {
        int4 d = reinterpret_cast<const int4*>(ut + EE)[i - Q];
        atomicAdd(&g_deg[NP + d.x], 1); atomicAdd(&g_deg[NP + d.y], 1);
        atomicAdd(&g_deg[NP + d.z], 1); atomicAdd(&g_deg[NP + d.w], 1);
    } else if (i < 3 * Q) {
        int4 d = reinterpret_cast<const int4*>(ug + EE)[i - 2 * Q];
        atomicAdd(&g_deg[NP + NT + d.x], 1); atomicAdd(&g_deg[NP + NT + d.y], 1);
        atomicAdd(&g_deg[NP + NT + d.z], 1); atomicAdd(&g_deg[NP + NT + d.w], 1);
    }
}

// single-pass scan: block-local prefix + atomic global base.
__global__ void scanA_kernel() {
    __shared__ int wsum[8];
    __shared__ int blockBase;
    int t = threadIdx.x, lane = t & 31, wid = t >> 5;
    int idx = blockIdx.x * 1024 + t * 4;

    int v0 = 0, v1 = 0, v2 = 0, v3 = 0;
    if (idx + 3 < NTOT) {
        int4 d4 = *reinterpret_cast<const int4*>(g_deg + idx);
        v0 = d4.x; v1 = d4.y; v2 = d4.z; v3 = d4.w;
    } else {
        if (idx     < NTOT) v0 = g_deg[idx];
        if (idx + 1 < NTOT) v1 = g_deg[idx + 1];
        if (idx + 2 < NTOT) v2 = g_deg[idx + 2];
        if (idx + 3 < NTOT) v3 = g_deg[idx + 3];
    }
    int s = v0 + v1 + v2 + v3;
    int inc = s;
#pragma unroll
    for (int o = 1; o < 32; o <<= 1) {
        int n = __shfl_up_sync(0xffffffffu, inc, o);
        if (lane >= o) inc += n;
    }
    if (lane == 31) wsum[wid] = inc;
    __syncthreads();
    if (t == 0) {
        int run = 0;
#pragma unroll
        for (int w = 0; w < 8; w++) { int x = wsum[w]; wsum[w] = run; run += x; }
        blockBase = atomicAdd(&g_total, run);
    }
    __syncthreads();
    int ex = blockBase + wsum[wid] + inc - s;
    if (idx     < NTOT) { g_off[idx]     = ex;                g_cur[idx]     = ex;
                          g_dinv[idx]     = v0 ? rsqrtf((float)v0) : 0.f; }
    if (idx + 1 < NTOT) { g_off[idx + 1] = ex + v0;           g_cur[idx + 1] = ex + v0;
                          g_dinv[idx + 1] = v1 ? rsqrtf((float)v1) : 0.f; }
    if (idx + 2 < NTOT) { g_off[idx + 2] = ex + v0 + v1;      g_cur[idx + 2] = ex + v0 + v1;
                          g_dinv[idx + 2] = v2 ? rsqrtf((float)v2) : 0.f; }
    if (idx + 3 < NTOT) { g_off[idx + 3] = ex + v0 + v1 + v2; g_cur[idx + 3] = ex + v0 + v1 + v2;
                          g_dinv[idx + 3] = v3 ? rsqrtf((float)v3) : 0.f; }
}

// convert + prescale: embs[n] = emb[n] * dinv[n]  (fp16), 8 elems/thread
__global__ void convert_kernel(const float* __restrict__ e0,
                               const float* __restrict__ e1,
                               const float* __restrict__ e2) {
    const int n0 = NP * DD / 8, n1 = NT * DD / 8, n2 = NG * DD / 8;
    int i = blockIdx.x * blockDim.x + threadIdx.x;
    const float4* src; __half* dst; int j; int nodeBase;
    if (i < n0)                { src = (const float4*)e0; dst = g_embs;                          j = i;            nodeBase = 0; }
    else if (i < n0 + n1)      { src = (const float4*)e1; dst = g_embs + (size_t)NP * DD;        j = i - n0;       nodeBase = NP; }
    else if (i < n0 + n1 + n2) { src = (const float4*)e2; dst = g_embs + (size_t)(NP + NT) * DD; j = i - n0 - n1;  nodeBase = NP + NT; }
    else return;
    int node = nodeBase + (j >> 3);             // 8 threads per row
    float w = g_dinv[node];
    float4 a = src[(size_t)j * 2], b = src[(size_t)j * 2 + 1];
    __half2 h0 = __floats2half2_rn(a.x * w, a.y * w), h1 = __floats2half2_rn(a.z * w, a.w * w);
    __half2 h2 = __floats2half2_rn(b.x * w, b.y * w), h3 = __floats2half2_rn(b.z * w, b.w * w);
    uint4 u;
    u.x = *reinterpret_cast<unsigned*>(&h0);
    u.y = *reinterpret_cast<unsigned*>(&h1);
    u.z = *reinterpret_cast<unsigned*>(&h2);
    u.w = *reinterpret_cast<unsigned*>(&h3);
    *reinterpret_cast<uint4*>(dst + (size_t)j * 8) = u;
}

__global__ void build_adj_kernel(const int* __restrict__ up,
                                 const int* __restrict__ ut,
                                 const int* __restrict__ ug) {
    const int Q = EE / 4;
    int i = blockIdx.x * blockDim.x + threadIdx.x;
    if (i < Q) {
        int4 s = reinterpret_cast<const int4*>(up)[i];
        int4 d = reinterpret_cast<const int4*>(up + EE)[i];
        g_adj[atomicAdd(&g_cur[d.x], 1)] = s.x;
        g_adj[atomicAdd(&g_cur[d.y], 1)] = s.y;
        g_adj[atomicAdd(&g_cur[d.z], 1)] = s.z;
        g_adj[atomicAdd(&g_cur[d.w], 1)] = s.w;
    } else if (i < 2 * Q) {
        int4 s = reinterpret_cast<const int4*>(ut)[i - Q];
        int4 d = reinterpret_cast<const int4*>(ut + EE)[i - Q];
        g_adj[atomicAdd(&g_cur[NP + d.x], 1)] = s.x;
        g_adj[atomicAdd(&g_cur[NP + d.y], 1)] = s.y;
        g_adj[atomicAdd(&g_cur[NP + d.z], 1)] = s.z;
        g_adj[atomicAdd(&g_cur[NP + d.w], 1)] = s.w;
    } else if (i < 3 * Q) {
        int4 s = reinterpret_cast<const int4*>(ug)[i - 2 * Q];
        int4 d = reinterpret_cast<const int4*>(ug + EE)[i - 2 * Q];
        g_adj[atomicAdd(&g_cur[NP + NT + d.x], 1)] = s.x;
        g_adj[atomicAdd(&g_cur[NP + NT + d.y], 1)] = s.y;
        g_adj[atomicAdd(&g_cur[NP + NT + d.z], 1)] = s.z;
        g_adj[atomicAdd(&g_cur[NP + NT + d.w], 1)] = s.w;
    }
}

// ---------------------------------------------------------------
__device__ __forceinline__ float4 load_h4(const __half* __restrict__ tab,
                                          int s, int o) {
    uint2 r = *reinterpret_cast<const uint2*>(tab + (size_t)s * DD + o);
    __half2 a = *reinterpret_cast<__half2*>(&r.x);
    __half2 b = *reinterpret_cast<__half2*>(&r.y);
    float2 fa = __half22float2(a), fb = __half22float2(b);
    return make_float4(fa.x, fa.y, fb.x, fb.y);
}

__device__ __forceinline__ void store_h4(__half* __restrict__ dst,
                                         int n, int o, float4 v) {
    __half2 a = __floats2half2_rn(v.x, v.y);
    __half2 b = __floats2half2_rn(v.z, v.w);
    uint2 u;
    u.x = *reinterpret_cast<unsigned*>(&a);
    u.y = *reinterpret_cast<unsigned*>(&b);
    *reinterpret_cast<uint2*>(dst + (size_t)n * DD + o) = u;
}

// plain-sum conv body over prescaled table (no per-edge weights)
__device__ __forceinline__ void conv_sum(const __half* __restrict__ tab,
                                         int beg, int end, int o, int hf,
                                         float4& acc) {
    int k = beg + hf;
    for (; k + 6 < end; k += 8) {
        int s0 = g_adj[k], s1 = g_adj[k + 2], s2 = g_adj[k + 4], s3 = g_adj[k + 6];
        float4 v0 = load_h4(tab, s0, o);
        float4 v1 = load_h4(tab, s1, o);
        float4 v2 = load_h4(tab, s2, o);
        float4 v3 = load_h4(tab, s3, o);
        acc.x += v0.x + v1.x + v2.x + v3.x;
        acc.y += v0.y + v1.y + v2.y + v3.y;
        acc.z += v0.z + v1.z + v2.z + v3.z;
        acc.w += v0.w + v1.w + v2.w + v3.w;
    }
    for (; k < end; k += 2) {
        int s = g_adj[k];
        float4 v = load_h4(tab, s, o);
        acc.x += v.x; acc.y += v.y; acc.z += v.z; acc.w += v.w;
    }
}

// conv1: sum prescaled emb rows; store x1 (true) and x1*dinv (prescaled)
__global__ void __launch_bounds__(256)
conv1_kernel() {
    int n = (blockIdx.x * blockDim.x + threadIdx.x) >> 5;
    if (n >= NTOT) return;
    int lane = threadIdx.x & 31;
    int hf = lane >> 4, sub = lane & 15;
    int o = sub << 2;

    int base = (n < NP) ? 0 : (n < NP + NT) ? NP : (NP + NT);
    const __half* tab = g_embs + (size_t)base * DD;

    int beg = g_off[n], end = beg + g_deg[n];
    float4 acc = make_float4(0.f, 0.f, 0.f, 0.f);
    conv_sum(tab, beg, end, o, hf, acc);

    acc.x += __shfl_xor_sync(0xffffffffu, acc.x, 16);
    acc.y += __shfl_xor_sync(0xffffffffu, acc.y, 16);
    acc.z += __shfl_xor_sync(0xffffffffu, acc.z, 16);
    acc.w += __shfl_xor_sync(0xffffffffu, acc.w, 16);

    if (hf == 0) {
        float wd = g_dinv[n];
        float4 x1 = make_float4(acc.x * wd, acc.y * wd, acc.z * wd, acc.w * wd);
        store_h4(g_x1h, n, o, x1);
        store_h4(g_x1s, n, o,
                 make_float4(x1.x * wd, x1.y * wd, x1.z * wd, x1.w * wd));
    }
}

// conv2: sum prescaled x1 rows; p = (emb + x1 + x2)/3 -> g_x2h
__global__ void __launch_bounds__(256)
conv2_kernel(const float* __restrict__ e0, const float* __restrict__ e1,
             const float* __restrict__ e2) {
    int n = (blockIdx.x * blockDim.x + threadIdx.x) >> 5;
    if (n >= NTOT) return;
    int lane = threadIdx.x & 31;
    int hf = lane >> 4, sub = lane & 15;
    int o = sub << 2;

    const float* emb;
    int base;
    if (n < NP)            { emb = e0; base = 0; }
    else if (n < NP + NT)  { emb = e1; base = NP; }
    else                   { emb = e2; base = NP + NT; }
    const __half* tab = g_x1s + (size_t)base * DD;

    int beg = g_off[n], end = beg + g_deg[n];
    float4 acc = make_float4(0.f, 0.f, 0.f, 0.f);
    conv_sum(tab, beg, end, o, hf, acc);

    acc.x += __shfl_xor_sync(0xffffffffu, acc.x, 16);
    acc.y += __shfl_xor_sync(0xffffffffu, acc.y, 16);
    acc.z += __shfl_xor_sync(0xffffffffu, acc.z, 16);
    acc.w += __shfl_xor_sync(0xffffffffu, acc.w, 16);

    if (hf == 0) {
        float wd = g_dinv[n];
        float4 ev  = *reinterpret_cast<const float4*>(emb + (size_t)(n - base) * DD + o);
        float4 x1v = load_h4(g_x1h, n, o);
        const float k3 = 1.f / 3.f;
        store_h4(g_x2h, n, o,
                 make_float4((ev.x + x1v.x + acc.x * wd) * k3,
                             (ev.y + x1v.y + acc.y * wd) * k3,
                             (ev.z + x1v.z + acc.z * wd) * k3,
                             (ev.w + x1v.w + acc.w * wd) * k3));
    }
}

// final: warp-per-edge-pair, weights in registers, 12 gathers in flight.
#define FSTEP(f, k, a)                                            \
    f.x = fmaf((a), w[k].x, f.x); f.y = fmaf((a), w[k].y, f.y);   \
    f.z = fmaf((a), w[k].z, f.z); f.w = fmaf((a), w[k].w, f.w);

__global__ void __launch_bounds__(128)
final_kernel(const int* __restrict__ up, const int* __restrict__ ut,
             const int* __restrict__ ug,
             const float* __restrict__ sfeat, const float* __restrict__ dfeat,
             const float* __restrict__ Ws, const float* __restrict__ bs,
             const float* __restrict__ Wd, const float* __restrict__ bd,
             float* __restrict__ out) {
    int t = threadIdx.x;
    int lane = t & 31;
    int hf = lane >> 4, sub = lane & 15;
    int o = sub << 2;

    const float* Wsel = hf ? Wd : Ws;
    const float* Bsel = hf ? bd : bs;
    const float* feat = hf ? dfeat : sfeat;

    float4 w[16];
#pragma unroll
    for (int k = 0; k < 16; k++)
        w[k] = *reinterpret_cast<const float4*>(Wsel + k * 64 + o);
    float4 bias = *reinterpret_cast<const float4*>(Bsel + o);

    const __half* P = g_x2h;
    const __half* T = g_x2h + (size_t)NP * DD;
    const __half* G = g_x2h + (size_t)(NP + NT) * DD;

    int warpId = (blockIdx.x * blockDim.x + t) >> 5;
    int nWarps = (gridDim.x * blockDim.x) >> 5;
    const float k3 = 1.f / 3.f;

    for (int e = warpId * 2; e < EE; e += nWarps * 2) {
        int eb = e + 1;
        int a0 = up[e + hf * EE],  a1 = ut[e + hf * EE],  a2 = ug[e + hf * EE];
        int b0 = up[eb + hf * EE], b1 = ut[eb + hf * EE], b2 = ug[eb + hf * EE];
        float4 pa = load_h4(P, a0, o), ta = load_h4(T, a1, o), ga = load_h4(G, a2, o);
        float4 pb = load_h4(P, b0, o), tb = load_h4(T, b1, o), gb = load_h4(G, b2, o);
        const float4* fxa = reinterpret_cast<const float4*>(feat + (size_t)e * 16);
        float4 xa0 = fxa[0], xa1 = fxa[1], xa2 = fxa[2], xa3 = fxa[3];
        float4 xb0 = fxa[4], xb1 = fxa[5], xb2 = fxa[6], xb3 = fxa[7];

        float4 fA = bias;
        FSTEP(fA, 0,  xa0.x) FSTEP(fA, 1,  xa0.y) FSTEP(fA, 2,  xa0.z) FSTEP(fA, 3,  xa0.w)
        FSTEP(fA, 4,  xa1.x) FSTEP(fA, 5,  xa1.y) FSTEP(fA, 6,  xa1.z) FSTEP(fA, 7,  xa1.w)
        FSTEP(fA, 8,  xa2.x) FSTEP(fA, 9,  xa2.y) FSTEP(fA, 10, xa2.z) FSTEP(fA, 11, xa2.w)
        FSTEP(fA, 12, xa3.x) FSTEP(fA, 13, xa3.y) FSTEP(fA, 14, xa3.z) FSTEP(fA, 15, xa3.w)

        float4 fB = bias;
        FSTEP(fB, 0,  xb0.x) FSTEP(fB, 1,  xb0.y) FSTEP(fB, 2,  xb0.z) FSTEP(fB, 3,  xb0.w)
        FSTEP(fB, 4,  xb1.x) FSTEP(fB, 5,  xb1.y) FSTEP(fB, 6,  xb1.z) FSTEP(fB, 7,  xb1.w)
        FSTEP(fB, 8,  xb2.x) FSTEP(fB, 9,  xb2.y) FSTEP(fB, 10, xb2.z) FSTEP(fB, 11, xb2.w)
        FSTEP(fB, 12, xb3.x) FSTEP(fB, 13, xb3.y) FSTEP(fB, 14, xb3.z) FSTEP(fB, 15, xb3.w)

        float4 meA, meB;
        meA.x = (pa.x + ta.x + ga.x) * k3 + fA.x;
        meA.y = (pa.y + ta.y + ga.y) * k3 + fA.y;
        meA.z = (pa.z + ta.z + ga.z) * k3 + fA.z;
        meA.w = (pa.w + ta.w + ga.w) * k3 + fA.w;
        meB.x = (pb.x + tb.x + gb.x) * k3 + fB.x;
        meB.y = (pb.y + tb.y + gb.y) * k3 + fB.y;
        meB.z = (pb.z + tb.z + gb.z) * k3 + fB.z;
        meB.w = (pb.w + tb.w + gb.w) * k3 + fB.w;

        float4 otA, otB;
        otA.x = __shfl_xor_sync(0xffffffffu, meA.x, 16);
        otA.y = __shfl_xor_sync(0xffffffffu, meA.y, 16);
        otA.z = __shfl_xor_sync(0xffffffffu, meA.z, 16);
        otA.w = __shfl_xor_sync(0xffffffffu, meA.w, 16);
        otB.x = __shfl_xor_sync(0xffffffffu, meB.x, 16);
        otB.y = __shfl_xor_sync(0xffffffffu, meB.y, 16);
        otB.z = __shfl_xor_sync(0xffffffffu, meB.z, 16);
        otB.w = __shfl_xor_sync(0xffffffffu, meB.w, 16);

        float pA = meA.x * otA.x + meA.y * otA.y + meA.z * otA.z + meA.w * otA.w;
        float pB = meB.x * otB.x + meB.y * otB.y + meB.z * otB.z + meB.w * otB.w;
#pragma unroll
        for (int off = 8; off; off >>= 1) {
            pA += __shfl_xor_sync(0xffffffffu, pA, off);
            pB += __shfl_xor_sync(0xffffffffu, pB, off);
        }
        if (lane == 0) { out[e] = pA; out[eb] = pB; }
    }
}

// ---------------------------------------------------------------
extern "C" void kernel_launch(void* const* d_in, const int* in_sizes, int n_in,
                              void* d_out, int out_size) {
    const int*   up     = (const int*)d_in[0];
    const int*   ut     = (const int*)d_in[1];
    const int*   ug     = (const int*)d_in[2];
    const float* sfeat  = (const float*)d_in[3];
    const float* dfeat  = (const float*)d_in[4];
    const float* up_emb = (const float*)d_in[5];
    const float* ut_emb = (const float*)d_in[6];
    const float* ug_emb = (const float*)d_in[7];
    const float* W_src  = (const float*)d_in[8];
    const float* b_src  = (const float*)d_in[9];
    const float* W_dst  = (const float*)d_in[10];
    const float* b_dst  = (const float*)d_in[11];
    float* out = (float*)d_out;

    void* degPtr = nullptr;  cudaGetSymbolAddress(&degPtr, g_deg);
    void* totPtr = nullptr;  cudaGetSymbolAddress(&totPtr, g_total);
    cudaMemsetAsync(degPtr, 0, NTOT * sizeof(int));
    cudaMemsetAsync(totPtr, 0, sizeof(int));

    degree_kernel<<<(3 * (EE / 4) + 255) / 256, 256>>>(up, ut, ug);
    scanA_kernel<<<SCAN_BLK, 256>>>();
    convert_kernel<<<(NTOT * DD / 8 + 255) / 256, 256>>>(up_emb, ut_emb, ug_emb);
    build_adj_kernel<<<(3 * (EE / 4) + 255) / 256, 256>>>(up, ut, ug);

    const int convGrid = (NTOT * 32 + 255) / 256;
    conv1_kernel<<<convGrid, 256>>>();                          // profiled slot
    conv2_kernel<<<convGrid, 256>>>(up_emb, ut_emb, ug_emb);

    final_kernel<<<4096, 128>>>(up, ut, ug, sfeat, dfeat,
                                W_src, b_src, W_dst, b_dst, out);
}

// round 9
// speedup vs baseline: 1.0093x; 1.0093x over previous
#include <cuda_runtime.h>
#include <cuda_fp16.h>

#define NP 110000
#define NT 20000
#define NG 10000
#define NTOT (NP + NT + NG)   // 140000
#define EE 500000
#define DD 64
#define QE (EE / 4)           // 125000

#define SCAN_BLK ((NTOT + 1023) / 1024)   // 137

// ---- scratch (static device memory; no allocations allowed) ----
__device__ int   g_deg[NTOT];
__device__ int   g_off[NTOT];
__device__ int   g_cur[NTOT];
__device__ int   g_total;
__device__ int   g_adj[3 * EE];
__device__ float g_dinv[NTOT];
__device__ __align__(16) __half g_embs[(size_t)NTOT * DD];  // emb * dinv (fp16)
__device__ __align__(16) __half g_x1h[(size_t)NTOT * DD];   // x1 (true)
__device__ __align__(16) __half g_x1s[(size_t)NTOT * DD];   // x1 * dinv
__device__ __align__(16) __half g_x2h[(size_t)NTOT * DD];   // final table p

// ---------------------------------------------------------------
// per-graph in-degree histogram (4 edges / thread)
__global__ void degree_g(const int* __restrict__ ed, int base) {
    int i = blockIdx.x * blockDim.x + threadIdx.x;
    if (i >= QE) return;
    int4 d = reinterpret_cast<const int4*>(ed + EE)[i];
    atomicAdd(&g_deg[base + d.x], 1);
    atomicAdd(&g_deg[base + d.y], 1);
    atomicAdd(&g_deg[base + d.z], 1);
    atomicAdd(&g_deg[base + d.w], 1);
}

// single-pass scan: block-local prefix + atomic global base.
__global__ void scanA_kernel() {
    __shared__ int wsum[8];
    __shared__ int blockBase;
    int t = threadIdx.x, lane = t & 31, wid = t >> 5;
    int idx = blockIdx.x * 1024 + t * 4;

    int v0 = 0, v1 = 0, v2 = 0, v3 = 0;
    if (idx + 3 < NTOT) {
        int4 d4 = *reinterpret_cast<const int4*>(g_deg + idx);
        v0 = d4.x; v1 = d4.y; v2 = d4.z; v3 = d4.w;
    } else {
        if (idx     < NTOT) v0 = g_deg[idx];
        if (idx + 1 < NTOT) v1 = g_deg[idx + 1];
        if (idx + 2 < NTOT) v2 = g_deg[idx + 2];
        if (idx + 3 < NTOT) v3 = g_deg[idx + 3];
    }
    int s = v0 + v1 + v2 + v3;
    int inc = s;
#pragma unroll
    for (int o = 1; o < 32; o <<= 1) {
        int n = __shfl_up_sync(0xffffffffu, inc, o);
        if (lane >= o) inc += n;
    }
    if (lane == 31) wsum[wid] = inc;
    __syncthreads();
    if (t == 0) {
        int run = 0;
#pragma unroll
        for (int w = 0; w < 8; w++) { int x = wsum[w]; wsum[w] = run; run += x; }
        blockBase = atomicAdd(&g_total, run);
    }
    __syncthreads();
    int ex = blockBase + wsum[wid] + inc - s;
    if (idx     < NTOT) { g_off[idx]     = ex;                g_cur[idx]     = ex;
                          g_dinv[idx]     = v0 ? rsqrtf((float)v0) : 0.f; }
    if (idx + 1 < NTOT) { g_off[idx + 1] = ex + v0;           g_cur[idx + 1] = ex + v0;
                          g_dinv[idx + 1] = v1 ? rsqrtf((float)v1) : 0.f; }
    if (idx + 2 < NTOT) { g_off[idx + 2] = ex + v0 + v1;      g_cur[idx + 2] = ex + v0 + v1;
                          g_dinv[idx + 2] = v2 ? rsqrtf((float)v2) : 0.f; }
    if (idx + 3 < NTOT) { g_off[idx + 3] = ex + v0 + v1 + v2; g_cur[idx + 3] = ex + v0 + v1 + v2;
                          g_dinv[idx + 3] = v3 ? rsqrtf((float)v3) : 0.f; }
}

// per-graph convert + prescale: embs = emb * dinv (fp16), 8 elems / thread
__global__ void convert_g(const float* __restrict__ emb, int base, int nNodes) {
    int i = blockIdx.x * blockDim.x + threadIdx.x;
    if (i >= nNodes * (DD / 8)) return;
    int node = base + (i >> 3);
    float w = g_dinv[node];
    const float4* src = reinterpret_cast<const float4*>(emb);
    float4 a = src[(size_t)i * 2], b = src[(size_t)i * 2 + 1];
    __half2 h0 = __floats2half2_rn(a.x * w, a.y * w), h1 = __floats2half2_rn(a.z * w, a.w * w);
    __half2 h2 = __floats2half2_rn(b.x * w, b.y * w), h3 = __floats2half2_rn(b.z * w, b.w * w);
    uint4 u;
    u.x = *reinterpret_cast<unsigned*>(&h0);
    u.y = *reinterpret_cast<unsigned*>(&h1);
    u.z = *reinterpret_cast<unsigned*>(&h2);
    u.w = *reinterpret_cast<unsigned*>(&h3);
    *reinterpret_cast<uint4*>(g_embs + (size_t)base * DD + (size_t)i * 8) = u;
}

// per-graph CSR scatter (4 edges / thread; stores LOCAL src ids)
__global__ void build_adj_g(const int* __restrict__ ed, int base) {
    int i = blockIdx.x * blockDim.x + threadIdx.x;
    if (i >= QE) return;
    int4 s = reinterpret_cast<const int4*>(ed)[i];
    int4 d = reinterpret_cast<const int4*>(ed + EE)[i];
    g_adj[atomicAdd(&g_cur[base + d.x], 1)] = s.x;
    g_adj[atomicAdd(&g_cur[base + d.y], 1)] = s.y;
    g_adj[atomicAdd(&g_cur[base + d.z], 1)] = s.z;
    g_adj[atomicAdd(&g_cur[base + d.w], 1)] = s.w;
}

// ---------------------------------------------------------------
__device__ __forceinline__ float4 load_h4(const __half* __restrict__ tab,
                                          int s, int o) {
    uint2 r = *reinterpret_cast<const uint2*>(tab + (size_t)s * DD + o);
    __half2 a = *reinterpret_cast<__half2*>(&r.x);
    __half2 b = *reinterpret_cast<__half2*>(&r.y);
    float2 fa = __half22float2(a), fb = __half22float2(b);
    return make_float4(fa.x, fa.y, fb.x, fb.y);
}

__device__ __forceinline__ void store_h4(__half* __restrict__ dst,
                                         int n, int o, float4 v) {
    __half2 a = __floats2half2_rn(v.x, v.y);
    __half2 b = __floats2half2_rn(v.z, v.w);
    uint2 u;
    u.x = *reinterpret_cast<unsigned*>(&a);
    u.y = *reinterpret_cast<unsigned*>(&b);
    *reinterpret_cast<uint2*>(dst + (size_t)n * DD + o) = u;
}

// plain-sum conv body over prescaled table (no per-edge weights)
__device__ __forceinline__ void conv_sum(const __half* __restrict__ tab,
                                         int beg, int end, int o, int hf,
                                         float4& acc) {
    int k = beg + hf;
    for (; k + 6 < end; k += 8) {
        int s0 = g_adj[k], s1 = g_adj[k + 2], s2 = g_adj[k + 4], s3 = g_adj[k + 6];
        float4 v0 = load_h4(tab, s0, o);
        float4 v1 = load_h4(tab, s1, o);
        float4 v2 = load_h4(tab, s2, o);
        float4 v3 = load_h4(tab, s3, o);
        acc.x += v0.x + v1.x + v2.x + v3.x;
        acc.y += v0.y + v1.y + v2.y + v3.y;
        acc.z += v0.z + v1.z + v2.z + v3.z;
        acc.w += v0.w + v1.w + v2.w + v3.w;
    }
    for (; k < end; k += 2) {
        int s = g_adj[k];
        float4 v = load_h4(tab, s, o);
        acc.x += v.x; acc.y += v.y; acc.z += v.z; acc.w += v.w;
    }
}

// per-graph conv1: sum prescaled emb rows; store x1 (true) + x1*dinv
__global__ void __launch_bounds__(256)
conv1_g(int base, int nNodes) {
    int ln = (blockIdx.x * blockDim.x + threadIdx.x) >> 5;
    if (ln >= nNodes) return;
    int n = base + ln;
    int lane = threadIdx.x & 31;
    int hf = lane >> 4, sub = lane & 15;
    int o = sub << 2;

    const __half* tab = g_embs + (size_t)base * DD;
    int beg = g_off[n], end = beg + g_deg[n];
    float4 acc = make_float4(0.f, 0.f, 0.f, 0.f);
    conv_sum(tab, beg, end, o, hf, acc);

    acc.x += __shfl_xor_sync(0xffffffffu, acc.x, 16);
    acc.y += __shfl_xor_sync(0xffffffffu, acc.y, 16);
    acc.z += __shfl_xor_sync(0xffffffffu, acc.z, 16);
    acc.w += __shfl_xor_sync(0xffffffffu, acc.w, 16);

    if (hf == 0) {
        float wd = g_dinv[n];
        float4 x1 = make_float4(acc.x * wd, acc.y * wd, acc.z * wd, acc.w * wd);
        store_h4(g_x1h, n, o, x1);
        store_h4(g_x1s, n, o,
                 make_float4(x1.x * wd, x1.y * wd, x1.z * wd, x1.w * wd));
    }
}

// per-graph conv2 + finalize: p = (emb + x1 + x2)/3 -> g_x2h
__global__ void __launch_bounds__(256)
conv2_g(const float* __restrict__ emb, int base, int nNodes) {
    int ln = (blockIdx.x * blockDim.x + threadIdx.x) >> 5;
    if (ln >= nNodes) return;
    int n = base + ln;
    int lane = threadIdx.x & 31;
    int hf = lane >> 4, sub = lane & 15;
    int o = sub << 2;

    const __half* tab = g_x1s + (size_t)base * DD;
    int beg = g_off[n], end = beg + g_deg[n];
    float4 acc = make_float4(0.f, 0.f, 0.f, 0.f);
    conv_sum(tab, beg, end, o, hf, acc);

    acc.x += __shfl_xor_sync(0xffffffffu, acc.x, 16);
    acc.y += __shfl_xor_sync(0xffffffffu, acc.y, 16);
    acc.z += __shfl_xor_sync(0xffffffffu, acc.z, 16);
    acc.w += __shfl_xor_sync(0xffffffffu, acc.w, 16);

    if (hf == 0) {
        float wd = g_dinv[n];
        float4 ev  = *reinterpret_cast<const float4*>(emb + (size_t)ln * DD + o);
        float4 x1v = load_h4(g_x1h, n, o);
        const float k3 = 1.f / 3.f;
        store_h4(g_x2h, n, o,
                 make_float4((ev.x + x1v.x + acc.x * wd) * k3,
                             (ev.y + x1v.y + acc.y * wd) * k3,
                             (ev.z + x1v.z + acc.z * wd) * k3,
                             (ev.w + x1v.w + acc.w * wd) * k3));
    }
}

// final: warp-per-edge-pair, weights in registers, 12 gathers in flight.
#define FSTEP(f, k, a)                                            \
    f.x = fmaf((a), w[k].x, f.x); f.y = fmaf((a), w[k].y, f.y);   \
    f.z = fmaf((a), w[k].z, f.z); f.w = fmaf((a), w[k].w, f.w);

__global__ void __launch_bounds__(128)
final_kernel(const int* __restrict__ up, const int* __restrict__ ut,
             const int* __restrict__ ug,
             const float* __restrict__ sfeat, const float* __restrict__ dfeat,
             const float* __restrict__ Ws, const float* __restrict__ bs,
             const float* __restrict__ Wd, const float* __restrict__ bd,
             float* __restrict__ out) {
    int t = threadIdx.x;
    int lane = t & 31;
    int hf = lane >> 4, sub = lane & 15;
    int o = sub << 2;

    const float* Wsel = hf ? Wd : Ws;
    const float* Bsel = hf ? bd : bs;
    const float* feat = hf ? dfeat : sfeat;

    float4 w[16];
#pragma unroll
    for (int k = 0; k < 16; k++)
        w[k] = *reinterpret_cast<const float4*>(Wsel + k * 64 + o);
    float4 bias = *reinterpret_cast<const float4*>(Bsel + o);

    const __half* P = g_x2h;
    const __half* T = g_x2h + (size_t)NP * DD;
    const __half* G = g_x2h + (size_t)(NP + NT) * DD;

    int warpId = (blockIdx.x * blockDim.x + t) >> 5;
    int nWarps = (gridDim.x * blockDim.x) >> 5;
    const float k3 = 1.f / 3.f;

    for (int e = warpId * 2; e < EE; e += nWarps * 2) {
        int eb = e + 1;
        int a0 = up[e + hf * EE],  a1 = ut[e + hf * EE],  a2 = ug[e + hf * EE];
        int b0 = up[eb + hf * EE], b1 = ut[eb + hf * EE], b2 = ug[eb + hf * EE];
        float4 pa = load_h4(P, a0, o), ta = load_h4(T, a1, o), ga = load_h4(G, a2, o);
        float4 pb = load_h4(P, b0, o), tb = load_h4(T, b1, o), gb = load_h4(G, b2, o);
        const float4* fxa = reinterpret_cast<const float4*>(feat + (size_t)e * 16);
        float4 xa0 = fxa[0], xa1 = fxa[1], xa2 = fxa[2], xa3 = fxa[3];
        float4 xb0 = fxa[4], xb1 = fxa[5], xb2 = fxa[6], xb3 = fxa[7];

        float4 fA = bias;
        FSTEP(fA, 0,  xa0.x) FSTEP(fA, 1,  xa0.y) FSTEP(fA, 2,  xa0.z) FSTEP(fA, 3,  xa0.w)
        FSTEP(fA, 4,  xa1.x) FSTEP(fA, 5,  xa1.y) FSTEP(fA, 6,  xa1.z) FSTEP(fA, 7,  xa1.w)
        FSTEP(fA, 8,  xa2.x) FSTEP(fA, 9,  xa2.y) FSTEP(fA, 10, xa2.z) FSTEP(fA, 11, xa2.w)
        FSTEP(fA, 12, xa3.x) FSTEP(fA, 13, xa3.y) FSTEP(fA, 14, xa3.z) FSTEP(fA, 15, xa3.w)

        float4 fB = bias;
        FSTEP(fB, 0,  xb0.x) FSTEP(fB, 1,  xb0.y) FSTEP(fB, 2,  xb0.z) FSTEP(fB, 3,  xb0.w)
        FSTEP(fB, 4,  xb1.x) FSTEP(fB, 5,  xb1.y) FSTEP(fB, 6,  xb1.z) FSTEP(fB, 7,  xb1.w)
        FSTEP(fB, 8,  xb2.x) FSTEP(fB, 9,  xb2.y) FSTEP(fB, 10, xb2.z) FSTEP(fB, 11, xb2.w)
        FSTEP(fB, 12, xb3.x) FSTEP(fB, 13, xb3.y) FSTEP(fB, 14, xb3.z) FSTEP(fB, 15, xb3.w)

        float4 meA, meB;
        meA.x = (pa.x + ta.x + ga.x) * k3 + fA.x;
        meA.y = (pa.y + ta.y + ga.y) * k3 + fA.y;
        meA.z = (pa.z + ta.z + ga.z) * k3 + fA.z;
        meA.w = (pa.w + ta.w + ga.w) * k3 + fA.w;
        meB.x = (pb.x + tb.x + gb.x) * k3 + fB.x;
        meB.y = (pb.y + tb.y + gb.y) * k3 + fB.y;
        meB.z = (pb.z + tb.z + gb.z) * k3 + fB.z;
        meB.w = (pb.w + tb.w + gb.w) * k3 + fB.w;

        float4 otA, otB;
        otA.x = __shfl_xor_sync(0xffffffffu, meA.x, 16);
        otA.y = __shfl_xor_sync(0xffffffffu, meA.y, 16);
        otA.z = __shfl_xor_sync(0xffffffffu, meA.z, 16);
        otA.w = __shfl_xor_sync(0xffffffffu, meA.w, 16);
        otB.x = __shfl_xor_sync(0xffffffffu, meB.x, 16);
        otB.y = __shfl_xor_sync(0xffffffffu, meB.y, 16);
        otB.z = __shfl_xor_sync(0xffffffffu, meB.z, 16);
        otB.w = __shfl_xor_sync(0xffffffffu, meB.w, 16);

        float pA = meA.x * otA.x + meA.y * otA.y + meA.z * otA.z + meA.w * otA.w;
        float pB = meB.x * otB.x + meB.y * otB.y + meB.z * otB.z + meB.w * otB.w;
#pragma unroll
        for (int off = 8; off; off >>= 1) {
            pA += __shfl_xor_sync(0xffffffffu, pA, off);
            pB += __shfl_xor_sync(0xffffffffu, pB, off);
        }
        if (lane == 0) { out[e] = pA; out[eb] = pB; }
    }
}

// ---------------------------------------------------------------
extern "C" void kernel_launch(void* const* d_in, const int* in_sizes, int n_in,
                              void* d_out, int out_size) {
    const int*   up     = (const int*)d_in[0];
    const int*   ut     = (const int*)d_in[1];
    const int*   ug     = (const int*)d_in[2];
    const float* sfeat  = (const float*)d_in[3];
    const float* dfeat  = (const float*)d_in[4];
    const float* up_emb = (const float*)d_in[5];
    const float* ut_emb = (const float*)d_in[6];
    const float* ug_emb = (const float*)d_in[7];
    const float* W_src  = (const float*)d_in[8];
    const float* b_src  = (const float*)d_in[9];
    const float* W_dst  = (const float*)d_in[10];
    const float* b_dst  = (const float*)d_in[11];
    float* out = (float*)d_out;

    const int* eds[3]      = { up, ut, ug };
    const float* embs[3]   = { up_emb, ut_emb, ug_emb };
    const int bases[3]     = { 0, NP, NP + NT };
    const int counts[3]    = { NP, NT, NG };

    cudaStream_t s[3];
    for (int g = 0; g < 3; g++) cudaStreamCreateWithFlags(&s[g], cudaStreamNonBlocking);
    cudaEvent_t evFork, evDeg[3], evScan, evDone[3];
    cudaEventCreateWithFlags(&evFork, cudaEventDisableTiming);
    cudaEventCreateWithFlags(&evScan, cudaEventDisableTiming);
    for (int g = 0; g < 3; g++) {
        cudaEventCreateWithFlags(&evDeg[g], cudaEventDisableTiming);
        cudaEventCreateWithFlags(&evDone[g], cudaEventDisableTiming);
    }

    void* degPtr = nullptr;  cudaGetSymbolAddress(&degPtr, g_deg);
    void* totPtr = nullptr;  cudaGetSymbolAddress(&totPtr, g_total);
    cudaMemsetAsync(degPtr, 0, NTOT * sizeof(int));
    cudaMemsetAsync(totPtr, 0, sizeof(int));

    // fork: per-graph degree histograms (concurrent, latency-bound)
    cudaEventRecord(evFork, 0);
    const int degGrid = (QE + 255) / 256;
    for (int g = 0; g < 3; g++) {
        cudaStreamWaitEvent(s[g], evFork, 0);
        degree_g<<<degGrid, 256, 0, s[g]>>>(eds[g], bases[g]);
        cudaEventRecord(evDeg[g], s[g]);
    }
    for (int g = 0; g < 3; g++) cudaStreamWaitEvent(0, evDeg[g], 0);

    // join: global scan
    scanA_kernel<<<SCAN_BLK, 256>>>();
    cudaEventRecord(evScan, 0);

    // fork: per-graph pipelines build_adj -> convert -> conv1 -> conv2
    for (int g = 0; g < 3; g++) {
        cudaStreamWaitEvent(s[g], evScan, 0);
        build_adj_g<<<degGrid, 256, 0, s[g]>>>(eds[g], bases[g]);
        int cvGrid = (counts[g] * (DD / 8) + 255) / 256;
        convert_g<<<cvGrid, 256, 0, s[g]>>>(embs[g], bases[g], counts[g]);
        int c1Grid = (counts[g] * 32 + 255) / 256;
        conv1_g<<<c1Grid, 256, 0, s[g]>>>(bases[g], counts[g]);
        conv2_g<<<c1Grid, 256, 0, s[g]>>>(embs[g], bases[g], counts[g]);
        cudaEventRecord(evDone[g], s[g]);
    }
    for (int g = 0; g < 3; g++) cudaStreamWaitEvent(0, evDone[g], 0);

    // join: fused per-edge output (single resident wave)
    final_kernel<<<148 * 16, 128>>>(up, ut, ug, sfeat, dfeat,
                                    W_src, b_src, W_dst, b_dst, out);

    for (int g = 0; g < 3; g++) {
        cudaEventDestroy(evDeg[g]);
        cudaEventDestroy(evDone[g]);
        cudaStreamDestroy(s[g]);
    }
    cudaEventDestroy(evFork);
    cudaEventDestroy(evScan);
}

// round 10
// speedup vs baseline: 1.2489x; 1.2374x over previous
#include <cuda_runtime.h>
#include <cuda_fp16.h>

#define NP 110000
#define NT 20000
#define NG 10000
#define NTOT (NP + NT + NG)   // 140000
#define EE 500000
#define DD 64
#define QE (EE / 4)           // 125000

#define SCAN_BLK ((NTOT + 1023) / 1024)   // 137

typedef unsigned long long u64;

// ---- scratch (static device memory; no allocations allowed) ----
__device__ int   g_deg[NTOT];
__device__ int   g_off[NTOT];
__device__ int   g_cur[NTOT];
__device__ int   g_total;
__device__ int   g_adj[3 * EE];
__device__ float g_dinv[NTOT];
__device__ __align__(16) __half g_embs[(size_t)NTOT * DD];  // emb * dinv (fp16)
__device__ __align__(16) __half g_x1h[(size_t)NTOT * DD];   // x1 (true)
__device__ __align__(16) __half g_x1s[(size_t)NTOT * DD];   // x1 * dinv
__device__ __align__(16) __half g_x2h[(size_t)NTOT * DD];   // final table p

// ---------------------------------------------------------------
// packed fp32x2 helpers (sm_103a FFMA2 path)
__device__ __forceinline__ u64 pk2(float x, float y) {
    u64 r;
    asm("mov.b64 %0, {%1, %2};" : "=l"(r)
        : "r"(__float_as_uint(x)), "r"(__float_as_uint(y)));
    return r;
}
__device__ __forceinline__ u64 dup2(float a) {
    u64 r;
    asm("mov.b64 %0, {%1, %1};" : "=l"(r) : "r"(__float_as_uint(a)));
    return r;
}
__device__ __forceinline__ void pfma(u64& d, u64 a, u64 b) {
    asm("fma.rn.f32x2 %0, %1, %2, %0;" : "+l"(d) : "l"(a), "l"(b));
}
__device__ __forceinline__ float2 unpk2(u64 v) {
    float2 f;
    asm("mov.b64 {%0, %1}, %2;" : "=f"(f.x), "=f"(f.y) : "l"(v));
    return f;
}

// ---------------------------------------------------------------
// per-graph in-degree histogram (4 edges / thread)
__global__ void degree_g(const int* __restrict__ ed, int base) {
    int i = blockIdx.x * blockDim.x + threadIdx.x;
    if (i >= QE) return;
    int4 d = reinterpret_cast<const int4*>(ed + EE)[i];
    atomicAdd(&g_deg[base + d.x], 1);
    atomicAdd(&g_deg[base + d.y], 1);
    atomicAdd(&g_deg[base + d.z], 1);
    atomicAdd(&g_deg[base + d.w], 1);
}

// single-pass scan: block-local prefix + atomic global base.
__global__ void scanA_kernel() {
    __shared__ int wsum[8];
    __shared__ int blockBase;
    int t = threadIdx.x, lane = t & 31, wid = t >> 5;
    int idx = blockIdx.x * 1024 + t * 4;

    int v0 = 0, v1 = 0, v2 = 0, v3 = 0;
    if (idx + 3 < NTOT) {
        int4 d4 = *reinterpret_cast<const int4*>(g_deg + idx);
        v0 = d4.x; v1 = d4.y; v2 = d4.z; v3 = d4.w;
    } else {
        if (idx     < NTOT) v0 = g_deg[idx];
        if (idx + 1 < NTOT) v1 = g_deg[idx + 1];
        if (idx + 2 < NTOT) v2 = g_deg[idx + 2];
        if (idx + 3 < NTOT) v3 = g_deg[idx + 3];
    }
    int s = v0 + v1 + v2 + v3;
    int inc = s;
#pragma unroll
    for (int o = 1; o < 32; o <<= 1) {
        int n = __shfl_up_sync(0xffffffffu, inc, o);
        if (lane >= o) inc += n;
    }
    if (lane == 31) wsum[wid] = inc;
    __syncthreads();
    if (t == 0) {
        int run = 0;
#pragma unroll
        for (int w = 0; w < 8; w++) { int x = wsum[w]; wsum[w] = run; run += x; }
        blockBase = atomicAdd(&g_total, run);
    }
    __syncthreads();
    int ex = blockBase + wsum[wid] + inc - s;
    if (idx     < NTOT) { g_off[idx]     = ex;                g_cur[idx]     = ex;
                          g_dinv[idx]     = v0 ? rsqrtf((float)v0) : 0.f; }
    if (idx + 1 < NTOT) { g_off[idx + 1] = ex + v0;           g_cur[idx + 1] = ex + v0;
                          g_dinv[idx + 1] = v1 ? rsqrtf((float)v1) : 0.f; }
    if (idx + 2 < NTOT) { g_off[idx + 2] = ex + v0 + v1;      g_cur[idx + 2] = ex + v0 + v1;
                          g_dinv[idx + 2] = v2 ? rsqrtf((float)v2) : 0.f; }
    if (idx + 3 < NTOT) { g_off[idx + 3] = ex + v0 + v1 + v2; g_cur[idx + 3] = ex + v0 + v1 + v2;
                          g_dinv[idx + 3] = v3 ? rsqrtf((float)v3) : 0.f; }
}

// per-graph convert + prescale: embs = emb * dinv (fp16), 8 elems / thread
__global__ void convert_g(const float* __restrict__ emb, int base, int nNodes) {
    int i = blockIdx.x * blockDim.x + threadIdx.x;
    if (i >= nNodes * (DD / 8)) return;
    int node = base + (i >> 3);
    float w = g_dinv[node];
    const float4* src = reinterpret_cast<const float4*>(emb);
    float4 a = src[(size_t)i * 2], b = src[(size_t)i * 2 + 1];
    __half2 h0 = __floats2half2_rn(a.x * w, a.y * w), h1 = __floats2half2_rn(a.z * w, a.w * w);
    __half2 h2 = __floats2half2_rn(b.x * w, b.y * w), h3 = __floats2half2_rn(b.z * w, b.w * w);
    uint4 u;
    u.x = *reinterpret_cast<unsigned*>(&h0);
    u.y = *reinterpret_cast<unsigned*>(&h1);
    u.z = *reinterpret_cast<unsigned*>(&h2);
    u.w = *reinterpret_cast<unsigned*>(&h3);
    *reinterpret_cast<uint4*>(g_embs + (size_t)base * DD + (size_t)i * 8) = u;
}

// per-graph CSR scatter (4 edges / thread; stores LOCAL src ids)
__global__ void build_adj_g(const int* __restrict__ ed, int base) {
    int i = blockIdx.x * blockDim.x + threadIdx.x;
    if (i >= QE) return;
    int4 s = reinterpret_cast<const int4*>(ed)[i];
    int4 d = reinterpret_cast<const int4*>(ed + EE)[i];
    g_adj[atomicAdd(&g_cur[base + d.x], 1)] = s.x;
    g_adj[atomicAdd(&g_cur[base + d.y], 1)] = s.y;
    g_adj[atomicAdd(&g_cur[base + d.z], 1)] = s.z;
    g_adj[atomicAdd(&g_cur[base + d.w], 1)] = s.w;
}

// ---------------------------------------------------------------
// conv: 4 nodes per warp, 8 lanes per node (uint4 = 8 halves per lane),
// packed HADD2 accumulation, NO cross-lane reduce.
// acc = sum of prescaled rows; epilogue scales by dinv[n].

__device__ __forceinline__ void hacc(uint4& acc, uint4 r) {
    __half2* a = reinterpret_cast<__half2*>(&acc);
    __half2* b = reinterpret_cast<__half2*>(&r);
    a[0] = __hadd2(a[0], b[0]);
    a[1] = __hadd2(a[1], b[1]);
    a[2] = __hadd2(a[2], b[2]);
    a[3] = __hadd2(a[3], b[3]);
}

__global__ void __launch_bounds__(256)
conv1_g(int base, int nNodes) {
    int w = (blockIdx.x * blockDim.x + threadIdx.x) >> 5;
    int lane = threadIdx.x & 31;
    int slot = lane >> 3, sub = lane & 7;
    int ln = w * 4 + slot;
    bool valid = ln < nNodes;
    int n = base + ln;
    int beg = 0, deg = 0;
    if (valid) { beg = g_off[n]; deg = g_deg[n]; }
    int md = deg;
    md = max(md, __shfl_xor_sync(0xffffffffu, md, 8));
    md = max(md, __shfl_xor_sync(0xffffffffu, md, 16));

    const __half* tab = g_embs + (size_t)base * DD;
    uint4 accA = make_uint4(0, 0, 0, 0), accB = accA;

    int i = 0;
    for (; i + 1 < md; i += 2) {
        if (i < deg) {
            int s = g_adj[beg + i];
            uint4 r = *reinterpret_cast<const uint4*>(tab + (size_t)s * DD + sub * 8);
            hacc(accA, r);
        }
        if (i + 1 < deg) {
            int s = g_adj[beg + i + 1];
            uint4 r = *reinterpret_cast<const uint4*>(tab + (size_t)s * DD + sub * 8);
            hacc(accB, r);
        }
    }
    if (i < md && i < deg) {
        int s = g_adj[beg + i];
        uint4 r = *reinterpret_cast<const uint4*>(tab + (size_t)s * DD + sub * 8);
        hacc(accA, r);
    }
    hacc(accA, accB);

    if (valid) {
        float wd = g_dinv[n];
        __half2* a = reinterpret_cast<__half2*>(&accA);
        float2 f0 = __half22float2(a[0]), f1 = __half22float2(a[1]);
        float2 f2 = __half22float2(a[2]), f3 = __half22float2(a[3]);
        // x1 = acc * wd
        __half2 x0 = __floats2half2_rn(f0.x * wd, f0.y * wd);
        __half2 x1 = __floats2half2_rn(f1.x * wd, f1.y * wd);
        __half2 x2 = __floats2half2_rn(f2.x * wd, f2.y * wd);
        __half2 x3 = __floats2half2_rn(f3.x * wd, f3.y * wd);
        uint4 ux;
        ux.x = *reinterpret_cast<unsigned*>(&x0);
        ux.y = *reinterpret_cast<unsigned*>(&x1);
        ux.z = *reinterpret_cast<unsigned*>(&x2);
        ux.w = *reinterpret_cast<unsigned*>(&x3);
        *reinterpret_cast<uint4*>(g_x1h + (size_t)n * DD + sub * 8) = ux;
        // x1s = x1 * wd
        float w2 = wd * wd;
        __half2 s0 = __floats2half2_rn(f0.x * w2, f0.y * w2);
        __half2 s1 = __floats2half2_rn(f1.x * w2, f1.y * w2);
        __half2 s2 = __floats2half2_rn(f2.x * w2, f2.y * w2);
        __half2 s3 = __floats2half2_rn(f3.x * w2, f3.y * w2);
        uint4 us;
        us.x = *reinterpret_cast<unsigned*>(&s0);
        us.y = *reinterpret_cast<unsigned*>(&s1);
        us.z = *reinterpret_cast<unsigned*>(&s2);
        us.w = *reinterpret_cast<unsigned*>(&s3);
        *reinterpret_cast<uint4*>(g_x1s + (size_t)n * DD + sub * 8) = us;
    }
}

__global__ void __launch_bounds__(256)
conv2_g(const float* __restrict__ emb, int base, int nNodes) {
    int w = (blockIdx.x * blockDim.x + threadIdx.x) >> 5;
    int lane = threadIdx.x & 31;
    int slot = lane >> 3, sub = lane & 7;
    int ln = w * 4 + slot;
    bool valid = ln < nNodes;
    int n = base + ln;
    int beg = 0, deg = 0;
    if (valid) { beg = g_off[n]; deg = g_deg[n]; }
    int md = deg;
    md = max(md, __shfl_xor_sync(0xffffffffu, md, 8));
    md = max(md, __shfl_xor_sync(0xffffffffu, md, 16));

    const __half* tab = g_x1s + (size_t)base * DD;
    uint4 accA = make_uint4(0, 0, 0, 0), accB = accA;

    int i = 0;
    for (; i + 1 < md; i += 2) {
        if (i < deg) {
            int s = g_adj[beg + i];
            uint4 r = *reinterpret_cast<const uint4*>(tab + (size_t)s * DD + sub * 8);
            hacc(accA, r);
        }
        if (i + 1 < deg) {
            int s = g_adj[beg + i + 1];
            uint4 r = *reinterpret_cast<const uint4*>(tab + (size_t)s * DD + sub * 8);
            hacc(accB, r);
        }
    }
    if (i < md && i < deg) {
        int s = g_adj[beg + i];
        uint4 r = *reinterpret_cast<const uint4*>(tab + (size_t)s * DD + sub * 8);
        hacc(accA, r);
    }
    hacc(accA, accB);

    if (valid) {
        float wd = g_dinv[n];
        __half2* a = reinterpret_cast<__half2*>(&accA);
        float2 f0 = __half22float2(a[0]), f1 = __half22float2(a[1]);
        float2 f2 = __half22float2(a[2]), f3 = __half22float2(a[3]);
        // emb row (fp32, 8 dims for this lane = 2 float4)
        const float4* ev = reinterpret_cast<const float4*>(emb + (size_t)ln * DD + sub * 8);
        float4 e0 = ev[0], e1 = ev[1];
        // x1 row (fp16)
        uint4 x1u = *reinterpret_cast<const uint4*>(g_x1h + (size_t)n * DD + sub * 8);
        __half2* x1p = reinterpret_cast<__half2*>(&x1u);
        float2 x0 = __half22float2(x1p[0]), x1 = __half22float2(x1p[1]);
        float2 x2 = __half22float2(x1p[2]), x3 = __half22float2(x1p[3]);
        const float k3 = 1.f / 3.f;
        __half2 p0 = __floats2half2_rn((e0.x + x0.x + f0.x * wd) * k3, (e0.y + x0.y + f0.y * wd) * k3);
        __half2 p1 = __floats2half2_rn((e0.z + x1.x + f1.x * wd) * k3, (e0.w + x1.y + f1.y * wd) * k3);
        __half2 p2 = __floats2half2_rn((e1.x + x2.x + f2.x * wd) * k3, (e1.y + x2.y + f2.y * wd) * k3);
        __half2 p3 = __floats2half2_rn((e1.z + x3.x + f3.x * wd) * k3, (e1.w + x3.y + f3.y * wd) * k3);
        uint4 up;
        up.x = *reinterpret_cast<unsigned*>(&p0);
        up.y = *reinterpret_cast<unsigned*>(&p1);
        up.z = *reinterpret_cast<unsigned*>(&p2);
        up.w = *reinterpret_cast<unsigned*>(&p3);
        *reinterpret_cast<uint4*>(g_x2h + (size_t)n * DD + sub * 8) = up;
    }
}

// ---------------------------------------------------------------
__device__ __forceinline__ float4 load_h4(const __half* __restrict__ tab,
                                          int s, int o) {
    uint2 r = *reinterpret_cast<const uint2*>(tab + (size_t)s * DD + o);
    __half2 a = *reinterpret_cast<__half2*>(&r.x);
    __half2 b = *reinterpret_cast<__half2*>(&r.y);
    float2 fa = __half22float2(a), fb = __half22float2(b);
    return make_float4(fa.x, fa.y, fb.x, fb.y);
}

// final: warp-per-edge-pair; weights in registers as packed f32x2; fma.rn.f32x2.
#define FSTEP2(f01, f23, k, a) do {            \
    u64 _a = dup2(a);                          \
    pfma(f01, _a, w01[k]);                     \
    pfma(f23, _a, w23[k]);                     \
} while (0)

__global__ void __launch_bounds__(128)
final_kernel(const int* __restrict__ up, const int* __restrict__ ut,
             const int* __restrict__ ug,
             const float* __restrict__ sfeat, const float* __restrict__ dfeat,
             const float* __restrict__ Ws, const float* __restrict__ bs,
             const float* __restrict__ Wd, const float* __restrict__ bd,
             float* __restrict__ out) {
    int t = threadIdx.x;
    int lane = t & 31;
    int hf = lane >> 4, sub = lane & 15;
    int o = sub << 2;

    const float* Wsel = hf ? Wd : Ws;
    const float* Bsel = hf ? bd : bs;
    const float* feat = hf ? dfeat : sfeat;

    u64 w01[16], w23[16];
#pragma unroll
    for (int k = 0; k < 16; k++) {
        float4 wv = *reinterpret_cast<const float4*>(Wsel + k * 64 + o);
        w01[k] = pk2(wv.x, wv.y);
        w23[k] = pk2(wv.z, wv.w);
    }
    float4 bv = *reinterpret_cast<const float4*>(Bsel + o);
    u64 b01 = pk2(bv.x, bv.y), b23 = pk2(bv.z, bv.w);

    const __half* P = g_x2h;
    const __half* T = g_x2h + (size_t)NP * DD;
    const __half* G = g_x2h + (size_t)(NP + NT) * DD;

    int warpId = (blockIdx.x * blockDim.x + t) >> 5;
    int nWarps = (gridDim.x * blockDim.x) >> 5;
    const float k3 = 1.f / 3.f;

    for (int e = warpId * 2; e < EE; e += nWarps * 2) {
        int eb = e + 1;
        int a0 = up[e + hf * EE],  a1 = ut[e + hf * EE],  a2 = ug[e + hf * EE];
        int b0 = up[eb + hf * EE], b1 = ut[eb + hf * EE], b2 = ug[eb + hf * EE];
        float4 pa = load_h4(P, a0, o), ta = load_h4(T, a1, o), ga = load_h4(G, a2, o);
        float4 pb = load_h4(P, b0, o), tb = load_h4(T, b1, o), gb = load_h4(G, b2, o);
        const float4* fxa = reinterpret_cast<const float4*>(feat + (size_t)e * 16);
        float4 xa0 = fxa[0], xa1 = fxa[1], xa2 = fxa[2], xa3 = fxa[3];
        float4 xb0 = fxa[4], xb1 = fxa[5], xb2 = fxa[6], xb3 = fxa[7];

        u64 fA01 = b01, fA23 = b23;
        FSTEP2(fA01, fA23, 0,  xa0.x); FSTEP2(fA01, fA23, 1,  xa0.y);
        FSTEP2(fA01, fA23, 2,  xa0.z); FSTEP2(fA01, fA23, 3,  xa0.w);
        FSTEP2(fA01, fA23, 4,  xa1.x); FSTEP2(fA01, fA23, 5,  xa1.y);
        FSTEP2(fA01, fA23, 6,  xa1.z); FSTEP2(fA01, fA23, 7,  xa1.w);
        FSTEP2(fA01, fA23, 8,  xa2.x); FSTEP2(fA01, fA23, 9,  xa2.y);
        FSTEP2(fA01, fA23, 10, xa2.z); FSTEP2(fA01, fA23, 11, xa2.w);
        FSTEP2(fA01, fA23, 12, xa3.x); FSTEP2(fA01, fA23, 13, xa3.y);
        FSTEP2(fA01, fA23, 14, xa3.z); FSTEP2(fA01, fA23, 15, xa3.w);

        u64 fB01 = b01, fB23 = b23;
        FSTEP2(fB01, fB23, 0,  xb0.x); FSTEP2(fB01, fB23, 1,  xb0.y);
        FSTEP2(fB01, fB23, 2,  xb0.z); FSTEP2(fB01, fB23, 3,  xb0.w);
        FSTEP2(fB01, fB23, 4,  xb1.x); FSTEP2(fB01, fB23, 5,  xb1.y);
        FSTEP2(fB01, fB23, 6,  xb1.z); FSTEP2(fB01, fB23, 7,  xb1.w);
        FSTEP2(fB01, fB23, 8,  xb2.x); FSTEP2(fB01, fB23, 9,  xb2.y);
        FSTEP2(fB01, fB23, 10, xb2.z); FSTEP2(fB01, fB23, 11, xb2.w);
        FSTEP2(fB01, fB23, 12, xb3.x); FSTEP2(fB01, fB23, 13, xb3.y);
        FSTEP2(fB01, fB23, 14, xb3.z); FSTEP2(fB01, fB23, 15, xb3.w);

        float2 fa01 = unpk2(fA01), fa23 = unpk2(fA23);
        float2 fb01 = unpk2(fB01), fb23 = unpk2(fB23);

        float4 meA, meB;
        meA.x = (pa.x + ta.x + ga.x) * k3 + fa01.x;
        meA.y = (pa.y + ta.y + ga.y) * k3 + fa01.y;
        meA.z = (pa.z + ta.z + ga.z) * k3 + fa23.x;
        meA.w = (pa.w + ta.w + ga.w) * k3 + fa23.y;
        meB.x = (pb.x + tb.x + gb.x) * k3 + fb01.x;
        meB.y = (pb.y + tb.y + gb.y) * k3 + fb01.y;
        meB.z = (pb.z + tb.z + gb.z) * k3 + fb23.x;
        meB.w = (pb.w + tb.w + gb.w) * k3 + fb23.y;

        float4 otA, otB;
        otA.x = __shfl_xor_sync(0xffffffffu, meA.x, 16);
        otA.y = __shfl_xor_sync(0xffffffffu, meA.y, 16);
        otA.z = __shfl_xor_sync(0xffffffffu, meA.z, 16);
        otA.w = __shfl_xor_sync(0xffffffffu, meA.w, 16);
        otB.x = __shfl_xor_sync(0xffffffffu, meB.x, 16);
        otB.y = __shfl_xor_sync(0xffffffffu, meB.y, 16);
        otB.z = __shfl_xor_sync(0xffffffffu, meB.z, 16);
        otB.w = __shfl_xor_sync(0xffffffffu, meB.w, 16);

        float pA = meA.x * otA.x + meA.y * otA.y + meA.z * otA.z + meA.w * otA.w;
        float pB = meB.x * otB.x + meB.y * otB.y + meB.z * otB.z + meB.w * otB.w;
#pragma unroll
        for (int off = 8; off; off >>= 1) {
            pA += __shfl_xor_sync(0xffffffffu, pA, off);
            pB += __shfl_xor_sync(0xffffffffu, pB, off);
        }
        if (lane == 0) { out[e] = pA; out[eb] = pB; }
    }
}

// ---------------------------------------------------------------
extern "C" void kernel_launch(void* const* d_in, const int* in_sizes, int n_in,
                              void* d_out, int out_size) {
    const int*   up     = (const int*)d_in[0];
    const int*   ut     = (const int*)d_in[1];
    const int*   ug     = (const int*)d_in[2];
    const float* sfeat  = (const float*)d_in[3];
    const float* dfeat  = (const float*)d_in[4];
    const float* up_emb = (const float*)d_in[5];
    const float* ut_emb = (const float*)d_in[6];
    const float* ug_emb = (const float*)d_in[7];
    const float* W_src  = (const float*)d_in[8];
    const float* b_src  = (const float*)d_in[9];
    const float* W_dst  = (const float*)d_in[10];
    const float* b_dst  = (const float*)d_in[11];
    float* out = (float*)d_out;

    const int* eds[3]    = { up, ut, ug };
    const float* embs[3] = { up_emb, ut_emb, ug_emb };
    const int bases[3]   = { 0, NP, NP + NT };
    const int counts[3]  = { NP, NT, NG };

    cudaStream_t s[3];
    for (int g = 0; g < 3; g++) cudaStreamCreateWithFlags(&s[g], cudaStreamNonBlocking);
    cudaEvent_t evFork, evDeg[3], evScan, evDone[3];
    cudaEventCreateWithFlags(&evFork, cudaEventDisableTiming);
    cudaEventCreateWithFlags(&evScan, cudaEventDisableTiming);
    for (int g = 0; g < 3; g++) {
        cudaEventCreateWithFlags(&evDeg[g], cudaEventDisableTiming);
        cudaEventCreateWithFlags(&evDone[g], cudaEventDisableTiming);
    }

    void* degPtr = nullptr;  cudaGetSymbolAddress(&degPtr, g_deg);
    void* totPtr = nullptr;  cudaGetSymbolAddress(&totPtr, g_total);
    cudaMemsetAsync(degPtr, 0, NTOT * sizeof(int));
    cudaMemsetAsync(totPtr, 0, sizeof(int));

    cudaEventRecord(evFork, 0);
    const int degGrid = (QE + 255) / 256;
    for (int g = 0; g < 3; g++) {
        cudaStreamWaitEvent(s[g], evFork, 0);
        degree_g<<<degGrid, 256, 0, s[g]>>>(eds[g], bases[g]);
        cudaEventRecord(evDeg[g], s[g]);
    }
    for (int g = 0; g < 3; g++) cudaStreamWaitEvent(0, evDeg[g], 0);

    scanA_kernel<<<SCAN_BLK, 256>>>();
    cudaEventRecord(evScan, 0);

    for (int g = 0; g < 3; g++) {
        cudaStreamWaitEvent(s[g], evScan, 0);
        build_adj_g<<<degGrid, 256, 0, s[g]>>>(eds[g], bases[g]);
        int cvGrid = (counts[g] * (DD / 8) + 255) / 256;
        convert_g<<<cvGrid, 256, 0, s[g]>>>(embs[g], bases[g], counts[g]);
        int nw = (counts[g] + 3) / 4;                 // warps (4 nodes each)
        int cGrid = (nw * 32 + 255) / 256;
        conv1_g<<<cGrid, 256, 0, s[g]>>>(bases[g], counts[g]);
        conv2_g<<<cGrid, 256, 0, s[g]>>>(embs[g], bases[g], counts[g]);
        cudaEventRecord(evDone[g], s[g]);
    }
    for (int g = 0; g < 3; g++) cudaStreamWaitEvent(0, evDone[g], 0);

    final_kernel<<<148 * 16, 128>>>(up, ut, ug, sfeat, dfeat,
                                    W_src, b_src, W_dst, b_dst, out);

    for (int g = 0; g < 3; g++) {
        cudaEventDestroy(evDeg[g]);
        cudaEventDestroy(evDone[g]);
        cudaStreamDestroy(s[g]);
    }
    cudaEventDestroy(evFork);
    cudaEventDestroy(evScan);
}

// round 13
// speedup vs baseline: 1.2670x; 1.0145x over previous
#include <cuda_runtime.h>
#include <cuda_fp16.h>

#define NP 110000
#define NT 20000
#define NG 10000
#define NTOT (NP + NT + NG)   // 140000
#define EE 500000
#define DD 64
#define QE (EE / 4)           // 125000

#define SCAN_BLK ((NTOT + 1023) / 1024)   // 137

typedef unsigned long long u64;

// ---- scratch (static device memory; no allocations allowed) ----
__device__ int   g_deg[NTOT];
__device__ int   g_off[NTOT];
__device__ int   g_cur[NTOT];
__device__ int   g_total;
__device__ int   g_adj[3 * EE];
__device__ float g_dinv[NTOT];
__device__ __align__(16) __half g_embs[(size_t)NTOT * DD];  // emb * dinv (fp16)
__device__ __align__(16) __half g_x1s[(size_t)NTOT * DD];   // x1 * dinv
__device__ __align__(16) __half g_x2h[(size_t)NTOT * DD];   // final table p (fp16)

// ---------------------------------------------------------------
// packed fp32x2 helpers (sm_103a FFMA2 path)
__device__ __forceinline__ u64 pk2(float x, float y) {
    u64 r;
    asm("mov.b64 %0, {%1, %2};" : "=l"(r)
        : "r"(__float_as_uint(x)), "r"(__float_as_uint(y)));
    return r;
}
__device__ __forceinline__ u64 dup2(float a) {
    u64 r;
    asm("mov.b64 %0, {%1, %1};" : "=l"(r) : "r"(__float_as_uint(a)));
    return r;
}
__device__ __forceinline__ void pfma(u64& d, u64 a, u64 b) {
    asm("fma.rn.f32x2 %0, %1, %2, %0;" : "+l"(d) : "l"(a), "l"(b));
}
__device__ __forceinline__ float2 unpk2(u64 v) {
    float2 f;
    asm("mov.b64 {%0, %1}, %2;" : "=f"(f.x), "=f"(f.y) : "l"(v));
    return f;
}

// ---------------------------------------------------------------
__global__ void degree_g(const int* __restrict__ ed, int base) {
    int i = blockIdx.x * blockDim.x + threadIdx.x;
    if (i >= QE) return;
    int4 d = reinterpret_cast<const int4*>(ed + EE)[i];
    atomicAdd(&g_deg[base + d.x], 1);
    atomicAdd(&g_deg[base + d.y], 1);
    atomicAdd(&g_deg[base + d.z], 1);
    atomicAdd(&g_deg[base + d.w], 1);
}

__global__ void scanA_kernel() {
    __shared__ int wsum[8];
    __shared__ int blockBase;
    int t = threadIdx.x, lane = t & 31, wid = t >> 5;
    int idx = blockIdx.x * 1024 + t * 4;

    int v0 = 0, v1 = 0, v2 = 0, v3 = 0;
    if (idx + 3 < NTOT) {
        int4 d4 = *reinterpret_cast<const int4*>(g_deg + idx);
        v0 = d4.x; v1 = d4.y; v2 = d4.z; v3 = d4.w;
    } else {
        if (idx     < NTOT) v0 = g_deg[idx];
        if (idx + 1 < NTOT) v1 = g_deg[idx + 1];
        if (idx + 2 < NTOT) v2 = g_deg[idx + 2];
        if (idx + 3 < NTOT) v3 = g_deg[idx + 3];
    }
    int s = v0 + v1 + v2 + v3;
    int inc = s;
#pragma unroll
    for (int o = 1; o < 32; o <<= 1) {
        int n = __shfl_up_sync(0xffffffffu, inc, o);
        if (lane >= o) inc += n;
    }
    if (lane == 31) wsum[wid] = inc;
    __syncthreads();
    if (t == 0) {
        int run = 0;
#pragma unroll
        for (int w = 0; w < 8; w++) { int x = wsum[w]; wsum[w] = run; run += x; }
        blockBase = atomicAdd(&g_total, run);
    }
    __syncthreads();
    int ex = blockBase + wsum[wid] + inc - s;
    if (idx     < NTOT) { g_off[idx]     = ex;                g_cur[idx]     = ex;
                          g_dinv[idx]     = v0 ? rsqrtf((float)v0) : 0.f; }
    if (idx + 1 < NTOT) { g_off[idx + 1] = ex + v0;           g_cur[idx + 1] = ex + v0;
                          g_dinv[idx + 1] = v1 ? rsqrtf((float)v1) : 0.f; }
    if (idx + 2 < NTOT) { g_off[idx + 2] = ex + v0 + v1;      g_cur[idx + 2] = ex + v0 + v1;
                          g_dinv[idx + 2] = v2 ? rsqrtf((float)v2) : 0.f; }
    if (idx + 3 < NTOT) { g_off[idx + 3] = ex + v0 + v1 + v2; g_cur[idx + 3] = ex + v0 + v1 + v2;
                          g_dinv[idx + 3] = v3 ? rsqrtf((float)v3) : 0.f; }
}

__global__ void convert_g(const float* __restrict__ emb, int base, int nNodes) {
    int i = blockIdx.x * blockDim.x + threadIdx.x;
    if (i >= nNodes * (DD / 8)) return;
    int node = base + (i >> 3);
    float w = g_dinv[node];
    const float4* src = reinterpret_cast<const float4*>(emb);
    float4 a = src[(size_t)i * 2], b = src[(size_t)i * 2 + 1];
    __half2 h0 = __floats2half2_rn(a.x * w, a.y * w), h1 = __floats2half2_rn(a.z * w, a.w * w);
    __half2 h2 = __floats2half2_rn(b.x * w, b.y * w), h3 = __floats2half2_rn(b.z * w, b.w * w);
    uint4 u;
    u.x = *reinterpret_cast<unsigned*>(&h0);
    u.y = *reinterpret_cast<unsigned*>(&h1);
    u.z = *reinterpret_cast<unsigned*>(&h2);
    u.w = *reinterpret_cast<unsigned*>(&h3);
    *reinterpret_cast<uint4*>(g_embs + (size_t)base * DD + (size_t)i * 8) = u;
}

__global__ void build_adj_g(const int* __restrict__ ed, int base) {
    int i = blockIdx.x * blockDim.x + threadIdx.x;
    if (i >= QE) return;
    int4 s = reinterpret_cast<const int4*>(ed)[i];
    int4 d = reinterpret_cast<const int4*>(ed + EE)[i];
    g_adj[atomicAdd(&g_cur[base + d.x], 1)] = s.x;
    g_adj[atomicAdd(&g_cur[base + d.y], 1)] = s.y;
    g_adj[atomicAdd(&g_cur[base + d.z], 1)] = s.z;
    g_adj[atomicAdd(&g_cur[base + d.w], 1)] = s.w;
}

// ---------------------------------------------------------------
// conv: 4 nodes per warp, 8 lanes per node, packed HADD2 accumulation.
__device__ __forceinline__ void hacc(uint4& acc, uint4 r) {
    __half2* a = reinterpret_cast<__half2*>(&acc);
    __half2* b = reinterpret_cast<__half2*>(&r);
    a[0] = __hadd2(a[0], b[0]);
    a[1] = __hadd2(a[1], b[1]);
    a[2] = __hadd2(a[2], b[2]);
    a[3] = __hadd2(a[3], b[3]);
}

// conv1: acc = sum(emb_s * dinv_s); store ONLY x1s = acc * dinv^2
__global__ void __launch_bounds__(256)
conv1_g(int base, int nNodes) {
    int w = (blockIdx.x * blockDim.x + threadIdx.x) >> 5;
    int lane = threadIdx.x & 31;
    int slot = lane >> 3, sub = lane & 7;
    int ln = w * 4 + slot;
    bool valid = ln < nNodes;
    int n = base + ln;
    int beg = 0, deg = 0;
    if (valid) { beg = g_off[n]; deg = g_deg[n]; }
    int md = deg;
    md = max(md, __shfl_xor_sync(0xffffffffu, md, 8));
    md = max(md, __shfl_xor_sync(0xffffffffu, md, 16));

    const __half* tab = g_embs + (size_t)base * DD;
    uint4 accA = make_uint4(0, 0, 0, 0), accB = accA;

    int i = 0;
    for (; i + 1 < md; i += 2) {
        if (i < deg) {
            int s = g_adj[beg + i];
            hacc(accA, *reinterpret_cast<const uint4*>(tab + (size_t)s * DD + sub * 8));
        }
        if (i + 1 < deg) {
            int s = g_adj[beg + i + 1];
            hacc(accB, *reinterpret_cast<const uint4*>(tab + (size_t)s * DD + sub * 8));
        }
    }
    if (i < md && i < deg) {
        int s = g_adj[beg + i];
        hacc(accA, *reinterpret_cast<const uint4*>(tab + (size_t)s * DD + sub * 8));
    }
    hacc(accA, accB);

    if (valid) {
        float wd = g_dinv[n];
        float w2 = wd * wd;
        __half2* a = reinterpret_cast<__half2*>(&accA);
        float2 f0 = __half22float2(a[0]), f1 = __half22float2(a[1]);
        float2 f2 = __half22float2(a[2]), f3 = __half22float2(a[3]);
        __half2 s0 = __floats2half2_rn(f0.x * w2, f0.y * w2);
        __half2 s1 = __floats2half2_rn(f1.x * w2, f1.y * w2);
        __half2 s2 = __floats2half2_rn(f2.x * w2, f2.y * w2);
        __half2 s3 = __floats2half2_rn(f3.x * w2, f3.y * w2);
        uint4 us;
        us.x = *reinterpret_cast<unsigned*>(&s0);
        us.y = *reinterpret_cast<unsigned*>(&s1);
        us.z = *reinterpret_cast<unsigned*>(&s2);
        us.w = *reinterpret_cast<unsigned*>(&s3);
        *reinterpret_cast<uint4*>(g_x1s + (size_t)n * DD + sub * 8) = us;
    }
}

// conv2: acc = sum(x1s_neighbors); x1_own = x1s_own * sqrt(deg);
// p = (emb + x1 + acc*dinv)/3 -> g_x2h
__global__ void __launch_bounds__(256)
conv2_g(const float* __restrict__ emb, int base, int nNodes) {
    int w = (blockIdx.x * blockDim.x + threadIdx.x) >> 5;
    int lane = threadIdx.x & 31;
    int slot = lane >> 3, sub = lane & 7;
    int ln = w * 4 + slot;
    bool valid = ln < nNodes;
    int n = base + ln;
    int beg = 0, deg = 0;
    if (valid) { beg = g_off[n]; deg = g_deg[n]; }
    int md = deg;
    md = max(md, __shfl_xor_sync(0xffffffffu, md, 8));
    md = max(md, __shfl_xor_sync(0xffffffffu, md, 16));

    const __half* tab = g_x1s + (size_t)base * DD;
    uint4 accA = make_uint4(0, 0, 0, 0), accB = accA;

    int i = 0;
    for (; i + 1 < md; i += 2) {
        if (i < deg) {
            int s = g_adj[beg + i];
            hacc(accA, *reinterpret_cast<const uint4*>(tab + (size_t)s * DD + sub * 8));
        }
        if (i + 1 < deg) {
            int s = g_adj[beg + i + 1];
            hacc(accB, *reinterpret_cast<const uint4*>(tab + (size_t)s * DD + sub * 8));
        }
    }
    if (i < md && i < deg) {
        int s = g_adj[beg + i];
        hacc(accA, *reinterpret_cast<const uint4*>(tab + (size_t)s * DD + sub * 8));
    }
    hacc(accA, accB);

    if (valid) {
        float wd = g_dinv[n];
        float sq = sqrtf((float)deg);           // x1 = x1s * sqrt(deg); deg=0 -> 0
        __half2* a = reinterpret_cast<__half2*>(&accA);
        float2 f0 = __half22float2(a[0]), f1 = __half22float2(a[1]);
        float2 f2 = __half22float2(a[2]), f3 = __half22float2(a[3]);
        const float4* ev = reinterpret_cast<const float4*>(emb + (size_t)ln * DD + sub * 8);
        float4 e0 = ev[0], e1 = ev[1];
        uint4 x1u = *reinterpret_cast<const uint4*>(g_x1s + (size_t)n * DD + sub * 8);
        __half2* x1p = reinterpret_cast<__half2*>(&x1u);
        float2 x0 = __half22float2(x1p[0]), x1 = __half22float2(x1p[1]);
        float2 x2 = __half22float2(x1p[2]), x3 = __half22float2(x1p[3]);
        const float k3 = 1.f / 3.f;
        __half2 p0 = __floats2half2_rn((e0.x + x0.x * sq + f0.x * wd) * k3, (e0.y + x0.y * sq + f0.y * wd) * k3);
        __half2 p1 = __floats2half2_rn((e0.z + x1.x * sq + f1.x * wd) * k3, (e0.w + x1.y * sq + f1.y * wd) * k3);
        __half2 p2 = __floats2half2_rn((e1.x + x2.x * sq + f2.x * wd) * k3, (e1.y + x2.y * sq + f2.y * wd) * k3);
        __half2 p3 = __floats2half2_rn((e1.z + x3.x * sq + f3.x * wd) * k3, (e1.w + x3.y * sq + f3.y * wd) * k3);
        uint4 up;
        up.x = *reinterpret_cast<unsigned*>(&p0);
        up.y = *reinterpret_cast<unsigned*>(&p1);
        up.z = *reinterpret_cast<unsigned*>(&p2);
        up.w = *reinterpret_cast<unsigned*>(&p3);
        *reinterpret_cast<uint4*>(g_x2h + (size_t)n * DD + sub * 8) = up;
    }
}

// ---------------------------------------------------------------
__device__ __forceinline__ float4 load_h4(const __half* __restrict__ tab,
                                          int s, int o) {
    uint2 r = *reinterpret_cast<const uint2*>(tab + (size_t)s * DD + o);
    __half2 a = *reinterpret_cast<__half2*>(&r.x);
    __half2 b = *reinterpret_cast<__half2*>(&r.y);
    float2 fa = __half22float2(a), fb = __half22float2(b);
    return make_float4(fa.x, fa.y, fb.x, fb.y);
}

// final: warp-per-edge-pair; weights in registers as packed f32x2; fma.rn.f32x2.
#define FSTEP2(f01, f23, k, a) do {            \
    u64 _a = dup2(a);                          \
    pfma(f01, _a, w01[k]);                     \
    pfma(f23, _a, w23[k]);                     \
} while (0)

__global__ void __launch_bounds__(128)
final_kernel(const int* __restrict__ up, const int* __restrict__ ut,
             const int* __restrict__ ug,
             const float* __restrict__ sfeat, const float* __restrict__ dfeat,
             const float* __restrict__ Ws, const float* __restrict__ bs,
             const float* __restrict__ Wd, const float* __restrict__ bd,
             float* __restrict__ out) {
    int t = threadIdx.x;
    int lane = t & 31;
    int hf = lane >> 4, sub = lane & 15;
    int o = sub << 2;

    const float* Wsel = hf ? Wd : Ws;
    const float* Bsel = hf ? bd : bs;
    const float* feat = hf ? dfeat : sfeat;

    u64 w01[16], w23[16];
#pragma unroll
    for (int k = 0; k < 16; k++) {
        float4 wv = *reinterpret_cast<const float4*>(Wsel + k * 64 + o);
        w01[k] = pk2(wv.x, wv.y);
        w23[k] = pk2(wv.z, wv.w);
    }
    float4 bv = *reinterpret_cast<const float4*>(Bsel + o);
    u64 b01 = pk2(bv.x, bv.y), b23 = pk2(bv.z, bv.w);

    const __half* P = g_x2h;
    const __half* T = g_x2h + (size_t)NP * DD;
    const __half* G = g_x2h + (size_t)(NP + NT) * DD;

    int warpId = (blockIdx.x * blockDim.x + t) >> 5;
    int nWarps = (gridDim.x * blockDim.x) >> 5;
    const float k3 = 1.f / 3.f;

    for (int e = warpId * 2; e < EE; e += nWarps * 2) {
        int eb = e + 1;
        int a0 = up[e + hf * EE],  a1 = ut[e + hf * EE],  a2 = ug[e + hf * EE];
        int b0 = up[eb + hf * EE], b1 = ut[eb + hf * EE], b2 = ug[eb + hf * EE];
        float4 pa = load_h4(P, a0, o), ta = load_h4(T, a1, o), ga = load_h4(G, a2, o);
        float4 pb = load_h4(P, b0, o), tb = load_h4(T, b1, o), gb = load_h4(G, b2, o);
        const float4* fxa = reinterpret_cast<const float4*>(feat + (size_t)e * 16);
        float4 xa0 = fxa[0], xa1 = fxa[1], xa2 = fxa[2], xa3 = fxa[3];
        float4 xb0 = fxa[4], xb1 = fxa[5], xb2 = fxa[6], xb3 = fxa[7];

        u64 fA01 = b01, fA23 = b23;
        FSTEP2(fA01, fA23, 0,  xa0.x); FSTEP2(fA01, fA23, 1,  xa0.y);
        FSTEP2(fA01, fA23, 2,  xa0.z); FSTEP2(fA01, fA23, 3,  xa0.w);
        FSTEP2(fA01, fA23, 4,  xa1.x); FSTEP2(fA01, fA23, 5,  xa1.y);
        FSTEP2(fA01, fA23, 6,  xa1.z); FSTEP2(fA01, fA23, 7,  xa1.w);
        FSTEP2(fA01, fA23, 8,  xa2.x); FSTEP2(fA01, fA23, 9,  xa2.y);
        FSTEP2(fA01, fA23, 10, xa2.z); FSTEP2(fA01, fA23, 11, xa2.w);
        FSTEP2(fA01, fA23, 12, xa3.x); FSTEP2(fA01, fA23, 13, xa3.y);
        FSTEP2(fA01, fA23, 14, xa3.z); FSTEP2(fA01, fA23, 15, xa3.w);

        u64 fB01 = b01, fB23 = b23;
        FSTEP2(fB01, fB23, 0,  xb0.x); FSTEP2(fB01, fB23, 1,  xb0.y);
        FSTEP2(fB01, fB23, 2,  xb0.z); FSTEP2(fB01, fB23, 3,  xb0.w);
        FSTEP2(fB01, fB23, 4,  xb1.x); FSTEP2(fB01, fB23, 5,  xb1.y);
        FSTEP2(fB01, fB23, 6,  xb1.z); FSTEP2(fB01, fB23, 7,  xb1.w);
        FSTEP2(fB01, fB23, 8,  xb2.x); FSTEP2(fB01, fB23, 9,  xb2.y);
        FSTEP2(fB01, fB23, 10, xb2.z); FSTEP2(fB01, fB23, 11, xb2.w);
        FSTEP2(fB01, fB23, 12, xb3.x); FSTEP2(fB01, fB23, 13, xb3.y);
        FSTEP2(fB01, fB23, 14, xb3.z); FSTEP2(fB01, fB23, 15, xb3.w);

        float2 fa01 = unpk2(fA01), fa23 = unpk2(fA23);
        float2 fb01 = unpk2(fB01), fb23 = unpk2(fB23);

        float4 meA, meB;
        meA.x = (pa.x + ta.x + ga.x) * k3 + fa01.x;
        meA.y = (pa.y + ta.y + ga.y) * k3 + fa01.y;
        meA.z = (pa.z + ta.z + ga.z) * k3 + fa23.x;
        meA.w = (pa.w + ta.w + ga.w) * k3 + fa23.y;
        meB.x = (pb.x + tb.x + gb.x) * k3 + fb01.x;
        meB.y = (pb.y + tb.y + gb.y) * k3 + fb01.y;
        meB.z = (pb.z + tb.z + gb.z) * k3 + fb23.x;
        meB.w = (pb.w + tb.w + gb.w) * k3 + fb23.y;

        float4 otA, otB;
        otA.x = __shfl_xor_sync(0xffffffffu, meA.x, 16);
        otA.y = __shfl_xor_sync(0xffffffffu, meA.y, 16);
        otA.z = __shfl_xor_sync(0xffffffffu, meA.z, 16);
        otA.w = __shfl_xor_sync(0xffffffffu, meA.w, 16);
        otB.x = __shfl_xor_sync(0xffffffffu, meB.x, 16);
        otB.y = __shfl_xor_sync(0xffffffffu, meB.y, 16);
        otB.z = __shfl_xor_sync(0xffffffffu, meB.z, 16);
        otB.w = __shfl_xor_sync(0xffffffffu, meB.w, 16);

        float pA = meA.x * otA.x + meA.y * otA.y + meA.z * otA.z + meA.w * otA.w;
        float pB = meB.x * otB.x + meB.y * otB.y + meB.z * otB.z + meB.w * otB.w;
#pragma unroll
        for (int off = 8; off; off >>= 1) {
            pA += __shfl_xor_sync(0xffffffffu, pA, off);
            pB += __shfl_xor_sync(0xffffffffu, pB, off);
        }
        if (lane == 0) { out[e] = pA; out[eb] = pB; }
    }
}

// ---------------------------------------------------------------
extern "C" void kernel_launch(void* const* d_in, const int* in_sizes, int n_in,
                              void* d_out, int out_size) {
    const int*   up     = (const int*)d_in[0];
    const int*   ut     = (const int*)d_in[1];
    const int*   ug     = (const int*)d_in[2];
    const float* sfeat  = (const float*)d_in[3];
    const float* dfeat  = (const float*)d_in[4];
    const float* up_emb = (const float*)d_in[5];
    const float* ut_emb = (const float*)d_in[6];
    const float* ug_emb = (const float*)d_in[7];
    const float* W_src  = (const float*)d_in[8];
    const float* b_src  = (const float*)d_in[9];
    const float* W_dst  = (const float*)d_in[10];
    const float* b_dst  = (const float*)d_in[11];
    float* out = (float*)d_out;

    const int* eds[3]    = { up, ut, ug };
    const float* embs[3] = { up_emb, ut_emb, ug_emb };
    const int bases[3]   = { 0, NP, NP + NT };
    const int counts[3]  = { NP, NT, NG };

    cudaStream_t s[3];
    for (int g = 0; g < 3; g++) cudaStreamCreateWithFlags(&s[g], cudaStreamNonBlocking);
    cudaEvent_t evFork, evDeg[3], evScan, evDone[3];
    cudaEventCreateWithFlags(&evFork, cudaEventDisableTiming);
    cudaEventCreateWithFlags(&evScan, cudaEventDisableTiming);
    for (int g = 0; g < 3; g++) {
        cudaEventCreateWithFlags(&evDeg[g], cudaEventDisableTiming);
        cudaEventCreateWithFlags(&evDone[g], cudaEventDisableTiming);
    }

    void* degPtr = nullptr;  cudaGetSymbolAddress(&degPtr, g_deg);
    void* totPtr = nullptr;  cudaGetSymbolAddress(&totPtr, g_total);
    cudaMemsetAsync(degPtr, 0, NTOT * sizeof(int));
    cudaMemsetAsync(totPtr, 0, sizeof(int));

    cudaEventRecord(evFork, 0);
    const int degGrid = (QE + 255) / 256;
    for (int g = 0; g < 3; g++) {
        cudaStreamWaitEvent(s[g], evFork, 0);
        degree_g<<<degGrid, 256, 0, s[g]>>>(eds[g], bases[g]);
        cudaEventRecord(evDeg[g], s[g]);
    }
    for (int g = 0; g < 3; g++) cudaStreamWaitEvent(0, evDeg[g], 0);

    scanA_kernel<<<SCAN_BLK, 256>>>();
    cudaEventRecord(evScan, 0);

    for (int g = 0; g < 3; g++) {
        cudaStreamWaitEvent(s[g], evScan, 0);
        build_adj_g<<<degGrid, 256, 0, s[g]>>>(eds[g], bases[g]);
        int cvGrid = (counts[g] * (DD / 8) + 255) / 256;
        convert_g<<<cvGrid, 256, 0, s[g]>>>(embs[g], bases[g], counts[g]);
        int nw = (counts[g] + 3) / 4;
        int cGrid = (nw * 32 + 255) / 256;
        conv1_g<<<cGrid, 256, 0, s[g]>>>(bases[g], counts[g]);
        conv2_g<<<cGrid, 256, 0, s[g]>>>(embs[g], bases[g], counts[g]);
        cudaEventRecord(evDone[g], s[g]);
    }
    for (int g = 0; g < 3; g++) cudaStreamWaitEvent(0, evDone[g], 0);

    final_kernel<<<148 * 16, 128>>>(up, ut, ug, sfeat, dfeat,
                                    W_src, b_src, W_dst, b_dst, out);

    for (int g = 0; g < 3; g++) {
        cudaEventDestroy(evDeg[g]);
        cudaEventDestroy(evDone[g]);
        cudaStreamDestroy(s[g]);
    }
    cudaEventDestroy(evFork);
    cudaEventDestroy(evScan);
}